// round 9
// baseline (speedup 1.0000x reference)
#include <cuda_runtime.h>
#include <math.h>
#include <stdint.h>

#define S_ 7
#define H_ 56
#define W_ 56
#define WS 7
#define C_ 384
#define HEADS 12
#define NW 64
#define NTOK 344
#define NWIN 343
#define L_ (S_*H_*W_)          /* 21952 */
#define M1 (NW*NTOK)           /* 22016 */
#define HID 1536
#define EPS_LN 1e-5f
#define QSCALE 0.17677669529663687f  /* 32^-0.5 */

/* ---------------- scratch (static device globals; no allocation) -------- */
__device__ float g_xc     [(size_t)M1 * C_];
__device__ float g_qkv    [(size_t)M1 * 3 * C_];
__device__ float g_attnout[(size_t)M1 * C_];
__device__ float g_xres   [(size_t)L_ * C_];
__device__ float g_ln2    [(size_t)M1 * C_];
__device__ float g_hid    [(size_t)M1 * HID];
__device__ float g_bias   [(size_t)HEADS * NWIN * NWIN];
__device__ float g_wqkv   [(size_t)C_ * 3 * C_];   /* W^T [N][K] tf32 */
__device__ float g_wproj  [(size_t)C_ * C_];
__device__ float g_wfc1   [(size_t)C_ * HID];
__device__ float g_wfc2   [(size_t)HID * C_];

/* ---------------- helpers ---------------------------------------------- */
__device__ __forceinline__ float warp_sum(float v) {
    v += __shfl_xor_sync(0xffffffffu, v, 16);
    v += __shfl_xor_sync(0xffffffffu, v, 8);
    v += __shfl_xor_sync(0xffffffffu, v, 4);
    v += __shfl_xor_sync(0xffffffffu, v, 2);
    v += __shfl_xor_sync(0xffffffffu, v, 1);
    return v;
}
__device__ __forceinline__ float warp_max(float v) {
    v = fmaxf(v, __shfl_xor_sync(0xffffffffu, v, 16));
    v = fmaxf(v, __shfl_xor_sync(0xffffffffu, v, 8));
    v = fmaxf(v, __shfl_xor_sync(0xffffffffu, v, 4));
    v = fmaxf(v, __shfl_xor_sync(0xffffffffu, v, 2));
    v = fmaxf(v, __shfl_xor_sync(0xffffffffu, v, 1));
    return v;
}
__device__ __forceinline__ float gelu_f(float v) {
    return 0.5f * v * (1.f + erff(v * 0.7071067811865475f));
}
__device__ __forceinline__ float tf32r(float x) {
    uint32_t u;
    asm("cvt.rna.tf32.f32 %0, %1;" : "=r"(u) : "f"(x));
    return __uint_as_float(u);
}
__device__ __forceinline__ void cpa16(float* s, const float* g) {
    uint32_t sa = (uint32_t)__cvta_generic_to_shared(s);
    asm volatile("cp.async.cg.shared.global [%0], [%1], 16;\n" :: "r"(sa), "l"(g));
}
#define MMA_TF32(c4, a4, b2)                                                   \
    asm volatile(                                                              \
        "mma.sync.aligned.m16n8k8.row.col.f32.tf32.tf32.f32 "                  \
        "{%0,%1,%2,%3}, {%4,%5,%6,%7}, {%8,%9}, {%0,%1,%2,%3};\n"              \
        : "+f"((c4)[0]), "+f"((c4)[1]), "+f"((c4)[2]), "+f"((c4)[3])           \
        : "r"((a4)[0]), "r"((a4)[1]), "r"((a4)[2]), "r"((a4)[3]),              \
          "r"((b2)[0]), "r"((b2)[1]))
#define LDSM4(r0, r1, r2, r3, addr)                                            \
    asm volatile("ldmatrix.sync.aligned.m8n8.x4.shared.b16 {%0,%1,%2,%3}, [%4];" \
                 : "=r"(r0), "=r"(r1), "=r"(r2), "=r"(r3) : "r"(addr))
#define LDSM2(r0, r1, addr)                                                    \
    asm volatile("ldmatrix.sync.aligned.m8n8.x2.shared.b16 {%0,%1}, [%2];"     \
                 : "=r"(r0), "=r"(r1) : "r"(addr))

__device__ __forceinline__ int scatter_row(int l) {
    int s   = l / (H_ * W_);
    int rem = l % (H_ * W_);
    int h   = rem / W_;
    int w   = rem % W_;
    int s2 = (s >= 3) ? s - 3 : s + 4;
    int h2 = (h >= 3) ? h - 3 : h + 53;
    int w2 = (w >= 3) ? w - 3 : w + 53;
    int win = (h2 / WS) * 8 + (w2 / WS);
    int t   = s2 * 49 + (h2 % WS) * 7 + (w2 % WS);
    return win * NTOK + 1 + t;
}
__device__ __forceinline__ int unscatter_l(int win, int t) {
    int t0 = t - 1;
    int ts = t0 / 49, th = (t0 / 7) % 7, tw = t0 % 7;
    int wh = win >> 3, ww = win & 7;
    int h2 = wh * 7 + th, w2 = ww * 7 + tw;
    int s  = (ts <= 3) ? ts + 3 : ts - 4;
    int hh = (h2 <= 52) ? h2 + 3 : h2 - 53;
    int wo = (w2 <= 52) ? w2 + 3 : w2 - 53;
    return (s * H_ + hh) * W_ + wo;
}

/* ---------------- small kernels ----------------------------------------- */
/* paired tiled transpose + tf32 round: o[n*K+k] = tf32r(w[k*N+n]) for two
   matrices per launch (blockIdx.z selects).                                */
__global__ void wtrans_pair(const float* __restrict__ w0, float* __restrict__ o0,
                            int K0, int N0,
                            const float* __restrict__ w1, float* __restrict__ o1,
                            int K1, int N1) {
    __shared__ float t[32][33];
    const float* w = blockIdx.z ? w1 : w0;
    float*       o = blockIdx.z ? o1 : o0;
    int K = blockIdx.z ? K1 : K0;
    int N = blockIdx.z ? N1 : N0;
    int bn = blockIdx.x * 32, bk = blockIdx.y * 32;
    if (bn >= N || bk >= K) return;
    int tx = threadIdx.x, ty = threadIdx.y;
#pragma unroll
    for (int i = 0; i < 32; i += 8)
        t[ty + i][tx] = w[(size_t)(bk + ty + i) * N + bn + tx];
    __syncthreads();
#pragma unroll
    for (int i = 0; i < 32; i += 8)
        o[(size_t)(bn + ty + i) * K + bk + tx] = tf32r(t[tx][ty + i]);
}

__global__ void bias_pre(const float* __restrict__ bt) {
    int idx = blockIdx.x * blockDim.x + threadIdx.x;
    if (idx >= NWIN * NWIN) return;
    int i = idx / NWIN, j = idx % NWIN;
    int si = i / 49, hi = (i / 7) % 7, wi = i % 7;
    int sj = j / 49, hj = (j / 7) % 7, wj = j % 7;
    int r = (si - sj + 6) * 20 + (hi - hj + 6) * 13 + (wi - wj + 6);
#pragma unroll
    for (int h = 0; h < HEADS; h++)
        g_bias[(size_t)h * NWIN * NWIN + idx] = bt[r * HEADS + h];
}

__global__ void gt_copy(const float* __restrict__ gt) {
    int idx = blockIdx.x * blockDim.x + threadIdx.x;
    if (idx >= NW * C_) return;
    int w = idx / C_, c = idx % C_;
    g_xc[((size_t)w * NTOK) * C_ + c] = tf32r(gt[idx]);
}

__global__ void ln1_scatter(const float* __restrict__ x,
                            const float* __restrict__ g,
                            const float* __restrict__ b) {
    int gw   = (blockIdx.x * blockDim.x + threadIdx.x) >> 5;
    int lane = threadIdx.x & 31;
    if (gw >= L_) return;
    const float* xi = x + (size_t)gw * C_;
    float v[12];
    float sum = 0.f;
#pragma unroll
    for (int m = 0; m < 12; m++) { v[m] = xi[lane + m * 32]; sum += v[m]; }
    sum = warp_sum(sum);
    float mu = sum * (1.f / 384.f);
    float vs = 0.f;
#pragma unroll
    for (int m = 0; m < 12; m++) { float d = v[m] - mu; vs += d * d; }
    vs = warp_sum(vs);
    float rstd = rsqrtf(vs * (1.f / 384.f) + EPS_LN);
    float* o = g_xc + (size_t)scatter_row(gw) * C_;
#pragma unroll
    for (int m = 0; m < 12; m++) {
        int c = lane + m * 32;
        o[c] = tf32r((v[m] - mu) * rstd * g[c] + b[c]);
    }
}

__global__ void ln2_kernel(const float* __restrict__ g,
                           const float* __restrict__ b) {
    int gw   = (blockIdx.x * blockDim.x + threadIdx.x) >> 5;
    int lane = threadIdx.x & 31;
    if (gw >= L_) return;
    const float* xi = g_xres + (size_t)gw * C_;
    float v[12];
    float sum = 0.f;
#pragma unroll
    for (int m = 0; m < 12; m++) { v[m] = xi[lane + m * 32]; sum += v[m]; }
    sum = warp_sum(sum);
    float mu = sum * (1.f / 384.f);
    float vs = 0.f;
#pragma unroll
    for (int m = 0; m < 12; m++) { float d = v[m] - mu; vs += d * d; }
    vs = warp_sum(vs);
    float rstd = rsqrtf(vs * (1.f / 384.f) + EPS_LN);
    float* o = g_ln2 + (size_t)gw * C_;
#pragma unroll
    for (int m = 0; m < 12; m++) {
        int c = lane + m * 32;
        o[c] = tf32r((v[m] - mu) * rstd * g[c] + b[c]);
    }
}

/* ---------------- attention via tf32 mma + ldmatrix --------------------- */
#define KSTR 36
#define VSTR 40
#define SSTR 356
#define QSTR 36
#define NPAD 352
#define ATT2_SMEM ((NPAD*KSTR + NTOK*VSTR + 64*SSTR + 64*QSTR) * 4 + NTOK * 4)

__global__ __launch_bounds__(256, 1) void attn_mma() {
    extern __shared__ float sm[];
    float* Ks = sm;
    float* Vs = Ks + NPAD * KSTR;
    float* Ss = Vs + NTOK * VSTR;
    float* Qs = Ss + 64 * SSTR;
    int*  lab = (int*)(Qs + 64 * QSTR);

    int tid = threadIdx.x, lane = tid & 31, wid = tid >> 5;
    int win = blockIdx.x / HEADS, head = blockIdx.x % HEADS;
    const float* base = g_qkv + (size_t)win * NTOK * (3 * C_) + head * 32;

    uint32_t ks_s = (uint32_t)__cvta_generic_to_shared(Ks);
    uint32_t ss_s = (uint32_t)__cvta_generic_to_shared(Ss);
    uint32_t qs_s = (uint32_t)__cvta_generic_to_shared(Qs);

    for (int idx = tid; idx < NPAD * 32; idx += 256) {
        int n = idx >> 5, d = idx & 31;
        Ks[n * KSTR + d] = (n < NTOK) ? tf32r(base[(size_t)n * (3 * C_) + C_ + d]) : 0.f;
    }
    for (int idx = tid; idx < NTOK * 32; idx += 256) {
        int j = idx >> 5, d = idx & 31;
        Vs[j * VSTR + d] = tf32r(base[(size_t)j * (3 * C_) + 2 * C_ + d]);
    }
    int wh = win >> 3, ww = win & 7;
    for (int t = tid; t < NTOK; t += 256) {
        int lv = -1;
        if (t > 0) {
            int t0 = t - 1;
            int ts = t0 / 49, th = (t0 / 7) % 7, tw = t0 % 7;
            int hh = wh * 7 + th, wc = ww * 7 + tw;
            int ia = (ts < 4) ? 1 : 2;
            int ib = (hh < 49) ? 0 : ((hh < 53) ? 1 : 2);
            int ic = (wc < 49) ? 0 : ((wc < 53) ? 1 : 2);
            lv = ia * 9 + ib * 3 + ic;
        }
        lab[t] = lv;
    }
    __syncthreads();

    const float* bh = g_bias + (size_t)head * NWIN * NWIN;
    const int wm  = (wid & 1) * 32;
    const int wn  = (wid >> 1) * 88;
    const int wnO = (wid >> 1) * 8;

    const int r_off = (lane & 7) + ((lane >> 3) & 1) * 8;
    const int a_k4  = ((lane >> 4) & 1) * 4;
    const int b_n   = (lane & 7) + ((lane >> 4) & 1) * 8;
    const int b_k4  = ((lane >> 3) & 1) * 4;

    for (int qt = 0; qt < 6; qt++) {
        int qbase = qt * 64;
        for (int i = tid; i < 64 * 32; i += 256) {
            int m = i >> 5, d = i & 31;
            int r = qbase + m;
            float v = (r < NTOK) ? base[(size_t)r * (3 * C_) + d] * QSCALE : 0.f;
            Qs[m * QSTR + d] = tf32r(v);
        }
        __syncthreads();

        float c[2][11][4];
#pragma unroll
        for (int mt = 0; mt < 2; mt++)
#pragma unroll
            for (int nt = 0; nt < 11; nt++)
#pragma unroll
                for (int q = 0; q < 4; q++) c[mt][nt][q] = 0.f;

#pragma unroll
        for (int ks = 0; ks < 4; ks++) {
            uint32_t a[2][4], b[11][2];
#pragma unroll
            for (int mt = 0; mt < 2; mt++)
                LDSM4(a[mt][0], a[mt][1], a[mt][2], a[mt][3],
                      qs_s + ((wm + mt * 16 + r_off) * QSTR + ks * 8 + a_k4) * 4);
#pragma unroll
            for (int p = 0; p < 5; p++)
                LDSM4(b[2 * p][0], b[2 * p][1], b[2 * p + 1][0], b[2 * p + 1][1],
                      ks_s + ((wn + p * 16 + b_n) * KSTR + ks * 8 + b_k4) * 4);
            LDSM2(b[10][0], b[10][1],
                  ks_s + ((wn + 80 + (b_n & 7)) * KSTR + ks * 8 + b_k4) * 4);
#pragma unroll
            for (int nt = 0; nt < 11; nt++) {
                MMA_TF32(c[0][nt], a[0], b[nt]);
                MMA_TF32(c[1][nt], a[1], b[nt]);
            }
        }

#pragma unroll
        for (int mt = 0; mt < 2; mt++) {
            int r0 = wm + mt * 16 + (lane >> 2);
#pragma unroll
            for (int nt = 0; nt < 11; nt++) {
                int j0 = wn + nt * 8 + 2 * (lane & 3);
#pragma unroll
                for (int h = 0; h < 2; h++) {
                    int rr = r0 + h * 8;
                    int rg = qbase + rr;
                    float v0 = c[mt][nt][2 * h];
                    float v1 = c[mt][nt][2 * h + 1];
                    if (rg < NTOK && rg > 0) {
                        int lr = lab[rg];
                        if (j0 < NTOK && j0 > 0) {
                            v0 += bh[(rg - 1) * NWIN + (j0 - 1)];
                            if (lr != lab[j0]) v0 -= 100.f;
                        }
                        int j1 = j0 + 1;
                        if (j1 < NTOK) {
                            v1 += bh[(rg - 1) * NWIN + (j1 - 1)];
                            if (lr != lab[j1]) v1 -= 100.f;
                        }
                    }
                    if (j0 >= NTOK)     v0 = -1e30f;
                    if (j0 + 1 >= NTOK) v1 = -1e30f;
                    Ss[rr * SSTR + j0]     = v0;
                    Ss[rr * SSTR + j0 + 1] = v1;
                }
            }
        }
        __syncthreads();

#pragma unroll
        for (int i = 0; i < 8; i++) {
            int rr = wid * 8 + i;
            float s[11];
            float mx = -1e30f;
#pragma unroll
            for (int m = 0; m < 11; m++) {
                s[m] = Ss[rr * SSTR + lane + m * 32];
                mx = fmaxf(mx, s[m]);
            }
            mx = warp_max(mx);
            float sum = 0.f;
#pragma unroll
            for (int m = 0; m < 11; m++) {
                float e = __expf(s[m] - mx);
                s[m] = e; sum += e;
            }
            sum = warp_sum(sum);
            float inv = 1.f / sum;
#pragma unroll
            for (int m = 0; m < 11; m++)
                Ss[rr * SSTR + lane + m * 32] = tf32r(s[m] * inv);
        }
        __syncthreads();

        float o[2][4] = {};
#pragma unroll 4
        for (int kt = 0; kt < 43; kt++) {
            uint32_t b[2];
            int kr = kt * 8 + (lane & 3);
            int bc = wnO + (lane >> 2);
            b[0] = __float_as_uint(Vs[(kr    ) * VSTR + bc]);
            b[1] = __float_as_uint(Vs[(kr + 4) * VSTR + bc]);
#pragma unroll
            for (int mt = 0; mt < 2; mt++) {
                uint32_t a[4];
                LDSM4(a[0], a[1], a[2], a[3],
                      ss_s + ((wm + mt * 16 + r_off) * SSTR + kt * 8 + a_k4) * 4);
                MMA_TF32(o[mt], a, b);
            }
        }
#pragma unroll
        for (int mt = 0; mt < 2; mt++)
#pragma unroll
            for (int h = 0; h < 2; h++) {
                int rr = qbase + wm + mt * 16 + (lane >> 2) + h * 8;
                if (rr < NTOK) {
                    float2 v;
                    v.x = tf32r(o[mt][2 * h]);
                    v.y = tf32r(o[mt][2 * h + 1]);
                    *(float2*)&g_attnout[((size_t)win * NTOK + rr) * C_ +
                                         head * 32 + wnO + 2 * (lane & 3)] = v;
                }
            }
        __syncthreads();
    }
}

/* ---------------- TF32 tensor-core GEMM, 256x128 tiles ------------------ */
/* A [M][K] row-major; B = W^T [N][K] (n-major).
   8 warps = 4(M)x2(N), warp tile 64x64; 3-stage cp.async; ldmatrix frags.
   EPI: 0 none, 1 gelu, 2 +res->Cd, 3 swin-unscatter.                      */
#define ASTR 36
#define ABUF (256*ASTR)
#define BBUF (128*ASTR)
#define STG  (ABUF + BBUF)
#define GEMM_SMEM_BYTES (3 * STG * 4)   /* 165888 */

template<int EPI, int CVT>
__global__ __launch_bounds__(256, 1) void gemm_tc(const float* __restrict__ A,
                                                  const float* __restrict__ Bt,
                                                  const float* __restrict__ bias,
                                                  const float* __restrict__ res,
                                                  float* __restrict__ Cd,
                                                  float* __restrict__ gtout,
                                                  int Mstore, int N, int K) {
    extern __shared__ float sm[];
    const int tid = threadIdx.x, lane = tid & 31, wid = tid >> 5;
    const int bm = blockIdx.y * 256, bn = blockIdx.x * 128;
    const int wm = (wid & 3) * 64, wn = (wid >> 2) * 64;
    const uint32_t sm_s = (uint32_t)__cvta_generic_to_shared(sm);

    const int r_off = (lane & 7) + ((lane >> 3) & 1) * 8;
    const int a_k4  = ((lane >> 4) & 1) * 4;
    const int b_n   = (lane & 7) + ((lane >> 4) & 1) * 8;
    const int b_k4  = ((lane >> 3) & 1) * 4;

    float c[4][8][4];
#pragma unroll
    for (int i = 0; i < 4; i++)
#pragma unroll
        for (int j = 0; j < 8; j++)
#pragma unroll
            for (int k = 0; k < 4; k++) c[i][j][k] = 0.f;

    const int NK = K >> 5;

    auto issue = [&](int kt) {
        int p = kt % 3;
        float* As = sm + p * STG;
        float* Bs = As + ABUF;
        const float* Ag = A  + (size_t)bm * K + kt * 32;
        const float* Bg = Bt + (size_t)bn * K + kt * 32;
#pragma unroll
        for (int i = 0; i < 8; i++) {
            int idx = tid + i * 256;
            int r = idx >> 3, c4 = (idx & 7) * 4;
            cpa16(As + r * ASTR + c4, Ag + (size_t)r * K + c4);
        }
#pragma unroll
        for (int i = 0; i < 4; i++) {
            int idx = tid + i * 256;
            int r = idx >> 3, c4 = (idx & 7) * 4;
            cpa16(Bs + r * ASTR + c4, Bg + (size_t)r * K + c4);
        }
        asm volatile("cp.async.commit_group;\n");
    };

    issue(0);
    if (NK > 1) issue(1);

    for (int kt = 0; kt < NK; kt++) {
        if (kt + 1 < NK)
            asm volatile("cp.async.wait_group 1;\n");
        else
            asm volatile("cp.async.wait_group 0;\n");
        __syncthreads();
        if (kt + 2 < NK) issue(kt + 2);

        const int p = kt % 3;
        const uint32_t as_s = sm_s + p * STG * 4;
        const uint32_t bs_s = as_s + ABUF * 4;
#pragma unroll
        for (int ks = 0; ks < 4; ks++) {
            uint32_t a[4][4], b[8][2];
#pragma unroll
            for (int mt = 0; mt < 4; mt++)
                LDSM4(a[mt][0], a[mt][1], a[mt][2], a[mt][3],
                      as_s + ((wm + mt * 16 + r_off) * ASTR + ks * 8 + a_k4) * 4);
#pragma unroll
            for (int pp = 0; pp < 4; pp++)
                LDSM4(b[2 * pp][0], b[2 * pp][1], b[2 * pp + 1][0], b[2 * pp + 1][1],
                      bs_s + ((wn + pp * 16 + b_n) * ASTR + ks * 8 + b_k4) * 4);
#pragma unroll
            for (int mt = 0; mt < 4; mt++)
#pragma unroll
                for (int nt = 0; nt < 8; nt++)
                    MMA_TF32(c[mt][nt], a[mt], b[nt]);
        }
    }

    if (EPI == 3) {
#pragma unroll
        for (int mt = 0; mt < 4; mt++)
#pragma unroll
            for (int h = 0; h < 2; h++) {
                int row = bm + wm + mt * 16 + (lane >> 2) + h * 8;
                int win = row / NTOK, t = row % NTOK;
                float* dst;
                const float* xsrc = nullptr;
                if (t == 0) {
                    dst = gtout + (size_t)win * C_;
                } else {
                    int l = unscatter_l(win, t);
                    dst  = Cd  + (size_t)l * C_;
                    xsrc = res + (size_t)l * C_;
                }
#pragma unroll
                for (int nt = 0; nt < 8; nt++) {
                    int col = bn + wn + nt * 8 + 2 * (lane & 3);
                    float2 bb = *(const float2*)&bias[col];
                    float2 v;
                    v.x = c[mt][nt][2 * h]     + bb.x;
                    v.y = c[mt][nt][2 * h + 1] + bb.y;
                    if (xsrc) {
                        float2 rv = *(const float2*)&xsrc[col];
                        v.x += rv.x; v.y += rv.y;
                    }
                    *(float2*)&dst[col] = v;
                }
            }
    } else {
#pragma unroll
        for (int nt = 0; nt < 8; nt++) {
            int col = bn + wn + nt * 8 + 2 * (lane & 3);
            float2 bb = *(const float2*)&bias[col];
#pragma unroll
            for (int mt = 0; mt < 4; mt++) {
                int row0 = bm + wm + mt * 16 + (lane >> 2);
#pragma unroll
                for (int h = 0; h < 2; h++) {
                    int row = row0 + h * 8;
                    if (row < Mstore) {
                        float2 v;
                        v.x = c[mt][nt][2 * h]     + bb.x;
                        v.y = c[mt][nt][2 * h + 1] + bb.y;
                        if (EPI == 1) { v.x = gelu_f(v.x); v.y = gelu_f(v.y); }
                        size_t o = (size_t)row * N + col;
                        if (EPI == 2) {
                            float2 rv = *(const float2*)&res[o];
                            v.x += rv.x; v.y += rv.y;
                        }
                        if (CVT) { v.x = tf32r(v.x); v.y = tf32r(v.y); }
                        *(float2*)&Cd[o] = v;
                    }
                }
            }
        }
    }
}

/* ---------------- launch ------------------------------------------------ */
extern "C" void kernel_launch(void* const* d_in, const int* in_sizes, int n_in,
                              void* d_out, int out_size) {
    const float* x     = (const float*)d_in[0];
    const float* gt    = (const float*)d_in[1];
    const float* n1g   = (const float*)d_in[2];
    const float* n1b   = (const float*)d_in[3];
    const float* qkvw  = (const float*)d_in[4];
    const float* qkvb  = (const float*)d_in[5];
    const float* btab  = (const float*)d_in[6];
    const float* projw = (const float*)d_in[7];
    const float* projb = (const float*)d_in[8];
    const float* n2g   = (const float*)d_in[9];
    const float* n2b   = (const float*)d_in[10];
    const float* fc1w  = (const float*)d_in[11];
    const float* fc1b  = (const float*)d_in[12];
    const float* fc2w  = (const float*)d_in[13];
    const float* fc2b  = (const float*)d_in[14];
    float* out = (float*)d_out;

    float *xc, *qkv, *ao, *xres, *ln2b, *hb;
    float *wq, *wp, *w1, *w2;
    cudaGetSymbolAddress((void**)&xc,   g_xc);
    cudaGetSymbolAddress((void**)&qkv,  g_qkv);
    cudaGetSymbolAddress((void**)&ao,   g_attnout);
    cudaGetSymbolAddress((void**)&xres, g_xres);
    cudaGetSymbolAddress((void**)&ln2b, g_ln2);
    cudaGetSymbolAddress((void**)&hb,   g_hid);
    cudaGetSymbolAddress((void**)&wq,   g_wqkv);
    cudaGetSymbolAddress((void**)&wp,   g_wproj);
    cudaGetSymbolAddress((void**)&w1,   g_wfc1);
    cudaGetSymbolAddress((void**)&w2,   g_wfc2);

    cudaFuncSetAttribute(attn_mma,
                         cudaFuncAttributeMaxDynamicSharedMemorySize,
                         ATT2_SMEM);
    cudaFuncSetAttribute(gemm_tc<0, 0>,
                         cudaFuncAttributeMaxDynamicSharedMemorySize,
                         GEMM_SMEM_BYTES);
    cudaFuncSetAttribute(gemm_tc<1, 1>,
                         cudaFuncAttributeMaxDynamicSharedMemorySize,
                         GEMM_SMEM_BYTES);
    cudaFuncSetAttribute(gemm_tc<2, 0>,
                         cudaFuncAttributeMaxDynamicSharedMemorySize,
                         GEMM_SMEM_BYTES);
    cudaFuncSetAttribute(gemm_tc<3, 0>,
                         cudaFuncAttributeMaxDynamicSharedMemorySize,
                         GEMM_SMEM_BYTES);

    /* launches 0-4, so the qkv GEMM is capture index 5 for ncu (-s 5)     */
    dim3 tb(32, 8);
    wtrans_pair<<<dim3((3 * C_) / 32, C_ / 32, 2), tb>>>(
        qkvw, wq, C_, 3 * C_, projw, wp, C_, C_);
    wtrans_pair<<<dim3(HID / 32, HID / 32, 2), tb>>>(
        fc1w, w1, C_, HID, fc2w, w2, HID, C_);
    bias_pre   <<<(NWIN * NWIN + 255) / 256, 256>>>(btab);
    gt_copy    <<<(NW * C_ + 255) / 256, 256>>>(gt);
    ln1_scatter<<<L_ / 8, 256>>>(x, n1g, n1b);

    gemm_tc<0, 0><<<dim3((3 * C_) / 128, M1 / 256), 256, GEMM_SMEM_BYTES>>>(
        xc, wq, qkvb, nullptr, qkv, nullptr, M1, 3 * C_, C_);

    attn_mma<<<NW * HEADS, 256, ATT2_SMEM>>>();

    gemm_tc<3, 0><<<dim3(C_ / 128, M1 / 256), 256, GEMM_SMEM_BYTES>>>(
        ao, wp, projb, x, xres, out + (size_t)L_ * C_, M1, C_, C_);

    ln2_kernel<<<L_ / 8, 256>>>(n2g, n2b);

    gemm_tc<1, 1><<<dim3(HID / 128, M1 / 256), 256, GEMM_SMEM_BYTES>>>(
        ln2b, w1, fc1b, nullptr, hb, nullptr, M1, HID, C_);

    gemm_tc<2, 0><<<dim3(C_ / 128, M1 / 256), 256, GEMM_SMEM_BYTES>>>(
        hb, w2, fc2b, xres, out, nullptr, L_, C_, HID);
}